// round 3
// baseline (speedup 1.0000x reference)
#include <cuda_runtime.h>
#include <cstdint>

// Problem constants (LightGCN_2: N=100000 nodes, D=128, E=1600000 edges)
#define NN 100000
#define DD 128
#define EE 1600000
#define RATE 0.1f
#define INV_KEEP (1.0f / 0.9f)

// Static device scratch (allocation-free rule: __device__ globals)
__device__ __align__(16) float g_h0[NN * DD];   // h0 = emb[x]
__device__ __align__(16) float g_g [NN * DD];   // current dropout'd features
__device__ __align__(16) float g_h1[NN * DD];   // spmm layer-1 output

// ---------------------------------------------------------------------------
// vector fp32 reduction (no return) — sm_90+: red.global.add.v4.f32
// ---------------------------------------------------------------------------
__device__ __forceinline__ void red_add_v4(float* addr, float a, float b,
                                           float c, float d) {
    asm volatile("red.global.add.v4.f32 [%0], {%1, %2, %3, %4};"
                 :: "l"(addr), "f"(a), "f"(b), "f"(c), "f"(d)
                 : "memory");
}

// ---------------------------------------------------------------------------
// K0: zero the layer-1 accumulator
// ---------------------------------------------------------------------------
__global__ void zero_h1_kernel() {
    int t = blockIdx.x * blockDim.x + threadIdx.x;   // over N*D/4
    if (t < NN * DD / 4)
        reinterpret_cast<float4*>(g_h1)[t] = make_float4(0.f, 0.f, 0.f, 0.f);
}

// ---------------------------------------------------------------------------
// K1: h0 = emb[x];  g = dropout(h0, u1)
// One thread per 4 channels: t = i*32 + q  (q = 0..31)
// ---------------------------------------------------------------------------
__global__ void embed_dropout_kernel(const int* __restrict__ x,
                                     const float* __restrict__ emb,
                                     const float* __restrict__ u1) {
    int t = blockIdx.x * blockDim.x + threadIdx.x;   // over N*32
    if (t >= NN * (DD / 4)) return;
    int i = t >> 5;          // node
    int q = t & 31;          // float4 slot within row
    int xi = x[i];
    float4 h = reinterpret_cast<const float4*>(emb + (size_t)xi * DD)[q];
    float4 u = reinterpret_cast<const float4*>(u1)[t];
    float4 g;
    g.x = (u.x >= RATE) ? h.x * INV_KEEP : 0.f;
    g.y = (u.y >= RATE) ? h.y * INV_KEEP : 0.f;
    g.z = (u.z >= RATE) ? h.z * INV_KEEP : 0.f;
    g.w = (u.w >= RATE) ? h.w * INV_KEEP : 0.f;
    reinterpret_cast<float4*>(g_h0)[t] = h;
    reinterpret_cast<float4*>(g_g )[t] = g;
}

// ---------------------------------------------------------------------------
// K2/K4: COO SpMM via vector reductions.
// One warp handles 32 edges: metadata loaded coalesced per-lane, then
// shfl-broadcast; each lane owns 4 contiguous channels (float4).
//   phase 0: dst = g_h1,  scale = 1
//   phase 1: dst = d_out, scale = 1/3 (accumulates into pre-filled output)
// ---------------------------------------------------------------------------
__global__ void spmm_red_kernel(const int* __restrict__ rows,
                                const int* __restrict__ cols,
                                const float* __restrict__ vals,
                                float* __restrict__ out_ext,
                                int phase, float scale) {
    int gtid = blockIdx.x * blockDim.x + threadIdx.x;
    int warp = gtid >> 5;
    int lane = gtid & 31;
    int base = warp * 32;
    if (base >= EE) return;

    int   r = 0, c = 0;
    float v = 0.f;
    int e = base + lane;
    if (e < EE) { r = rows[e]; c = cols[e]; v = vals[e]; }

    const float* g = g_g;
    float* dst = (phase == 0) ? g_h1 : out_ext;

    int cnt = min(32, EE - base);
    for (int j = 0; j < cnt; j++) {
        int   rj = __shfl_sync(0xffffffffu, r, j);
        int   cj = __shfl_sync(0xffffffffu, c, j);
        float vj = __shfl_sync(0xffffffffu, v, j) * scale;

        float4 m = reinterpret_cast<const float4*>(g + (size_t)cj * DD)[lane];
        float* addr = dst + (size_t)rj * DD + lane * 4;
        red_add_v4(addr, vj * m.x, vj * m.y, vj * m.z, vj * m.w);
    }
}

// ---------------------------------------------------------------------------
// K3: g = dropout(h1, u2)   (pure elementwise, no gather)
// ---------------------------------------------------------------------------
__global__ void dropout2_kernel(const float* __restrict__ u2) {
    int t = blockIdx.x * blockDim.x + threadIdx.x;   // over N*D/4
    if (t >= NN * DD / 4) return;
    float4 h = reinterpret_cast<const float4*>(g_h1)[t];
    float4 u = reinterpret_cast<const float4*>(u2)[t];
    float4 g;
    g.x = (u.x >= RATE) ? h.x * INV_KEEP : 0.f;
    g.y = (u.y >= RATE) ? h.y * INV_KEEP : 0.f;
    g.z = (u.z >= RATE) ? h.z * INV_KEEP : 0.f;
    g.w = (u.w >= RATE) ? h.w * INV_KEEP : 0.f;
    reinterpret_cast<float4*>(g_g)[t] = g;
}

// ---------------------------------------------------------------------------
// K3b: out = (h0 + h1) / 3   — pre-fill so the 2nd spmm adds h2/3 in place
// ---------------------------------------------------------------------------
__global__ void init_out_kernel(float* __restrict__ out) {
    int t = blockIdx.x * blockDim.x + threadIdx.x;   // over N*D/4
    if (t >= NN * DD / 4) return;
    float4 a = reinterpret_cast<const float4*>(g_h0)[t];
    float4 b = reinterpret_cast<const float4*>(g_h1)[t];
    const float k = 1.0f / 3.0f;
    float4 o;
    o.x = (a.x + b.x) * k;
    o.y = (a.y + b.y) * k;
    o.z = (a.z + b.z) * k;
    o.w = (a.w + b.w) * k;
    reinterpret_cast<float4*>(out)[t] = o;
}

// ---------------------------------------------------------------------------
// kernel_launch — graph-capturable pipeline
// inputs: 0:x(int32)[N] 1:rows[E] 2:cols[E] 3:A_vals[E] 4:emb[N*D] 5:u1 6:u2
// ---------------------------------------------------------------------------
extern "C" void kernel_launch(void* const* d_in, const int* in_sizes, int n_in,
                              void* d_out, int out_size) {
    const int*   x    = (const int*)  d_in[0];
    const int*   rows = (const int*)  d_in[1];
    const int*   cols = (const int*)  d_in[2];
    const float* vals = (const float*)d_in[3];
    const float* emb  = (const float*)d_in[4];
    const float* u1   = (const float*)d_in[5];
    const float* u2   = (const float*)d_in[6];
    float* out = (float*)d_out;

    const int TPB = 256;
    const int nd4_blocks  = (NN * DD / 4 + TPB - 1) / TPB;   // 12500
    const int emb_blocks  = (NN * (DD / 4) + TPB - 1) / TPB; // 12500
    const int spmm_blocks = (EE + TPB - 1) / TPB;            // 6250 (1 thread/edge meta)

    zero_h1_kernel<<<nd4_blocks, TPB>>>();
    embed_dropout_kernel<<<emb_blocks, TPB>>>(x, emb, u1);
    spmm_red_kernel<<<spmm_blocks, TPB>>>(rows, cols, vals, out, 0, 1.0f);
    dropout2_kernel<<<nd4_blocks, TPB>>>(u2);
    init_out_kernel<<<nd4_blocks, TPB>>>(out);
    spmm_red_kernel<<<spmm_blocks, TPB>>>(rows, cols, vals, out, 1, 1.0f / 3.0f);
}

// round 4
// speedup vs baseline: 1.5241x; 1.5241x over previous
#include <cuda_runtime.h>
#include <cstdint>

// LightGCN_2: N=100000 nodes, D=128 channels, E=1600000 edges
#define NN 100000
#define DD 128
#define EE 1600000
#define RATE 0.1f
#define INV_KEEP (1.0f / 0.9f)

#define SCAN_BLK 1024
#define SCAN_GRID ((NN + SCAN_BLK - 1) / SCAN_BLK)   // 98

// ---------------------------------------------------------------------------
// Static device scratch (allocation-free rule: __device__ globals)
// ---------------------------------------------------------------------------
__device__ __align__(16) float g_h0[NN * DD];   // h0 = emb[x]
__device__ __align__(16) float g_h1[NN * DD];   // layer-1 spmm output
__device__ __align__(16) float g_ga[NN * DD];   // dropout(h0,u1)  (layer-1 input)
__device__ __align__(16) float g_gb[NN * DD];   // dropout(h1,u2)  (layer-2 input)

__device__ __align__(8)  uint2 g_cv[EE];        // CSR payload: {col, bits(val)}
__device__ int g_cnt[NN];                       // row histogram
__device__ int g_rowptr[NN + 1];                // CSR row pointers
__device__ int g_cursor[NN];                    // scatter cursors
__device__ int g_incl[SCAN_GRID * SCAN_BLK];    // inclusive-scan temp
__device__ int g_btot[SCAN_GRID];               // per-block totals
__device__ int g_boff[SCAN_GRID];               // per-block offsets

// ---------------------------------------------------------------------------
// K0: zero the row histogram
// ---------------------------------------------------------------------------
__global__ void zero_cnt_kernel() {
    int i = blockIdx.x * blockDim.x + threadIdx.x;
    if (i < NN) g_cnt[i] = 0;
}

// ---------------------------------------------------------------------------
// K1: h0 = emb[x];  g_a = dropout(h0, u1).  One thread per float4.
// ---------------------------------------------------------------------------
__global__ void embed_dropout_kernel(const int* __restrict__ x,
                                     const float* __restrict__ emb,
                                     const float* __restrict__ u1) {
    int t = blockIdx.x * blockDim.x + threadIdx.x;   // over N*32
    if (t >= NN * (DD / 4)) return;
    int i = t >> 5;
    int q = t & 31;
    int xi = x[i];
    float4 h = reinterpret_cast<const float4*>(emb + (size_t)xi * DD)[q];
    float4 u = reinterpret_cast<const float4*>(u1)[t];
    float4 g;
    g.x = (u.x >= RATE) ? h.x * INV_KEEP : 0.f;
    g.y = (u.y >= RATE) ? h.y * INV_KEEP : 0.f;
    g.z = (u.z >= RATE) ? h.z * INV_KEEP : 0.f;
    g.w = (u.w >= RATE) ? h.w * INV_KEEP : 0.f;
    reinterpret_cast<float4*>(g_h0)[t] = h;
    reinterpret_cast<float4*>(g_ga)[t] = g;
}

// ---------------------------------------------------------------------------
// K2: row histogram (REDG, no return)
// ---------------------------------------------------------------------------
__global__ void hist_kernel(const int* __restrict__ rows) {
    int e = blockIdx.x * blockDim.x + threadIdx.x;
    if (e < EE) atomicAdd(&g_cnt[rows[e]], 1);
}

// ---------------------------------------------------------------------------
// K3a: per-block inclusive scan (Hillis-Steele in smem) + block totals
// ---------------------------------------------------------------------------
__global__ void scan1_kernel() {
    __shared__ int s[SCAN_BLK];
    int tid = threadIdx.x;
    int i = blockIdx.x * SCAN_BLK + tid;
    int v = (i < NN) ? g_cnt[i] : 0;
    s[tid] = v;
    __syncthreads();
#pragma unroll
    for (int off = 1; off < SCAN_BLK; off <<= 1) {
        int add = (tid >= off) ? s[tid - off] : 0;
        __syncthreads();
        s[tid] += add;
        __syncthreads();
    }
    g_incl[i] = s[tid];
    if (tid == SCAN_BLK - 1) g_btot[blockIdx.x] = s[tid];
}

// ---------------------------------------------------------------------------
// K3b: exclusive scan of block totals (98 values, serial is fine)
// ---------------------------------------------------------------------------
__global__ void scan2_kernel() {
    if (threadIdx.x == 0) {
        int acc = 0;
        for (int b = 0; b < SCAN_GRID; b++) { g_boff[b] = acc; acc += g_btot[b]; }
    }
}

// ---------------------------------------------------------------------------
// K3c: row_ptr (exclusive) + cursor init
// ---------------------------------------------------------------------------
__global__ void scan3_kernel() {
    int i = blockIdx.x * SCAN_BLK + threadIdx.x;
    if (i < NN) {
        int ex = g_incl[i] - g_cnt[i] + g_boff[blockIdx.x];
        g_rowptr[i] = ex;
        g_cursor[i] = ex;
    }
    if (i == 0) g_rowptr[NN] = EE;
}

// ---------------------------------------------------------------------------
// K4: scatter edges into CSR order, packed {col, val}
// ---------------------------------------------------------------------------
__global__ void scatter_kernel(const int* __restrict__ rows,
                               const int* __restrict__ cols,
                               const float* __restrict__ vals) {
    int e = blockIdx.x * blockDim.x + threadIdx.x;
    if (e >= EE) return;
    int r = rows[e];
    int pos = atomicAdd(&g_cursor[r], 1);
    g_cv[pos] = make_uint2((unsigned)cols[e], __float_as_uint(vals[e]));
}

// ---------------------------------------------------------------------------
// K5/K6: CSR SpMM, warp per row, register accumulation, fused epilogues.
//   MODE 0: gather g_a; write h1 AND g_b = dropout(h1, u2)
//   MODE 1: gather g_b; write out = (h0 + h1 + acc) / 3
// ---------------------------------------------------------------------------
template <int MODE>
__global__ void spmm_csr_kernel(const float* __restrict__ u2,
                                float* __restrict__ out) {
    int gw   = (blockIdx.x * blockDim.x + threadIdx.x) >> 5;  // row
    int lane = threadIdx.x & 31;
    if (gw >= NN) return;

    int s = g_rowptr[gw];
    int e = g_rowptr[gw + 1];
    const float4* gsrc =
        reinterpret_cast<const float4*>(MODE == 0 ? g_ga : g_gb);

    float4 acc = make_float4(0.f, 0.f, 0.f, 0.f);

    for (int base = s; base < e; base += 32) {
        int j = base + lane;
        uint2 cv = make_uint2(0u, 0u);
        if (j < e) cv = g_cv[j];
        int cnt = min(32, e - base);

        int k = 0;
        for (; k + 4 <= cnt; k += 4) {
            int   c0 = __shfl_sync(0xffffffffu, (int)cv.x, k + 0);
            int   c1 = __shfl_sync(0xffffffffu, (int)cv.x, k + 1);
            int   c2 = __shfl_sync(0xffffffffu, (int)cv.x, k + 2);
            int   c3 = __shfl_sync(0xffffffffu, (int)cv.x, k + 3);
            float v0 = __uint_as_float(__shfl_sync(0xffffffffu, cv.y, k + 0));
            float v1 = __uint_as_float(__shfl_sync(0xffffffffu, cv.y, k + 1));
            float v2 = __uint_as_float(__shfl_sync(0xffffffffu, cv.y, k + 2));
            float v3 = __uint_as_float(__shfl_sync(0xffffffffu, cv.y, k + 3));
            // 4 independent gathers in flight (MLP=4)
            float4 m0 = gsrc[c0 * 32 + lane];
            float4 m1 = gsrc[c1 * 32 + lane];
            float4 m2 = gsrc[c2 * 32 + lane];
            float4 m3 = gsrc[c3 * 32 + lane];
            acc.x += v0 * m0.x; acc.y += v0 * m0.y; acc.z += v0 * m0.z; acc.w += v0 * m0.w;
            acc.x += v1 * m1.x; acc.y += v1 * m1.y; acc.z += v1 * m1.z; acc.w += v1 * m1.w;
            acc.x += v2 * m2.x; acc.y += v2 * m2.y; acc.z += v2 * m2.z; acc.w += v2 * m2.w;
            acc.x += v3 * m3.x; acc.y += v3 * m3.y; acc.z += v3 * m3.z; acc.w += v3 * m3.w;
        }
        for (; k < cnt; k++) {
            int   c = __shfl_sync(0xffffffffu, (int)cv.x, k);
            float v = __uint_as_float(__shfl_sync(0xffffffffu, cv.y, k));
            float4 m = gsrc[c * 32 + lane];
            acc.x += v * m.x; acc.y += v * m.y; acc.z += v * m.z; acc.w += v * m.w;
        }
    }

    int t = gw * 32 + lane;
    if (MODE == 0) {
        reinterpret_cast<float4*>(g_h1)[t] = acc;
        float4 u = reinterpret_cast<const float4*>(u2)[t];
        float4 g;
        g.x = (u.x >= RATE) ? acc.x * INV_KEEP : 0.f;
        g.y = (u.y >= RATE) ? acc.y * INV_KEEP : 0.f;
        g.z = (u.z >= RATE) ? acc.z * INV_KEEP : 0.f;
        g.w = (u.w >= RATE) ? acc.w * INV_KEEP : 0.f;
        reinterpret_cast<float4*>(g_gb)[t] = g;
    } else {
        float4 a = reinterpret_cast<const float4*>(g_h0)[t];
        float4 b = reinterpret_cast<const float4*>(g_h1)[t];
        const float kk = 1.0f / 3.0f;
        float4 o;
        o.x = (a.x + b.x + acc.x) * kk;
        o.y = (a.y + b.y + acc.y) * kk;
        o.z = (a.z + b.z + acc.z) * kk;
        o.w = (a.w + b.w + acc.w) * kk;
        reinterpret_cast<float4*>(out)[t] = o;
    }
}

// ---------------------------------------------------------------------------
// kernel_launch — graph-capturable pipeline
// inputs: 0:x(int32)[N] 1:rows[E] 2:cols[E] 3:A_vals[E] 4:emb[N*D] 5:u1 6:u2
// ---------------------------------------------------------------------------
extern "C" void kernel_launch(void* const* d_in, const int* in_sizes, int n_in,
                              void* d_out, int out_size) {
    const int*   x    = (const int*)  d_in[0];
    const int*   rows = (const int*)  d_in[1];
    const int*   cols = (const int*)  d_in[2];
    const float* vals = (const float*)d_in[3];
    const float* emb  = (const float*)d_in[4];
    const float* u1   = (const float*)d_in[5];
    const float* u2   = (const float*)d_in[6];
    float* out = (float*)d_out;

    const int TPB = 256;
    const int nd4_blocks  = (NN * (DD / 4) + TPB - 1) / TPB;  // 12500
    const int e_blocks    = (EE + TPB - 1) / TPB;             // 6250
    const int cnt_blocks  = (NN + TPB - 1) / TPB;             // 391
    const int spmm_blocks = (NN * 32 + TPB - 1) / TPB;        // 12500 (8 warps/blk)

    // CSR build
    zero_cnt_kernel<<<cnt_blocks, TPB>>>();
    hist_kernel<<<e_blocks, TPB>>>(rows);
    scan1_kernel<<<SCAN_GRID, SCAN_BLK>>>();
    scan2_kernel<<<1, 32>>>();
    scan3_kernel<<<SCAN_GRID, SCAN_BLK>>>();
    scatter_kernel<<<e_blocks, TPB>>>(rows, cols, vals);

    // Features
    embed_dropout_kernel<<<nd4_blocks, TPB>>>(x, emb, u1);

    // Layer 1: h1 = A g_a;  g_b = dropout(h1, u2)   (fused epilogue)
    spmm_csr_kernel<0><<<spmm_blocks, TPB>>>(u2, out);
    // Layer 2: out = (h0 + h1 + A g_b) / 3          (fused epilogue)
    spmm_csr_kernel<1><<<spmm_blocks, TPB>>>(u2, out);
}

// round 5
// speedup vs baseline: 1.5932x; 1.0453x over previous
#include <cuda_runtime.h>
#include <cuda_fp16.h>
#include <cstdint>

// LightGCN_2: N=100000 nodes, D=128 channels, E=1600000 edges
#define NN 100000
#define DD 128
#define EE 1600000
#define RATE 0.1f
#define INV_KEEP (1.0f / 0.9f)

#define SCAN_BLK 1024
#define SCAN_GRID ((NN + SCAN_BLK - 1) / SCAN_BLK)   // 98

// ---------------------------------------------------------------------------
// Static device scratch (allocation-free rule: __device__ globals)
// ---------------------------------------------------------------------------
__device__ __align__(16) float  g_h0[NN * DD];      // h0 = emb[x]        (fp32)
__device__ __align__(16) float  g_h1[NN * DD];      // layer-1 output     (fp32)
__device__ __align__(16) __half g_ga[NN * DD];      // dropout(h0,u1)     (fp16)
__device__ __align__(16) __half g_gb[NN * DD];      // dropout(h1,u2)     (fp16)

__device__ __align__(8)  uint2 g_cv[EE];            // CSR payload {col, val bits}
__device__ int g_cnt[NN];
__device__ int g_rowptr[NN + 1];
__device__ int g_cursor[NN];
__device__ int g_incl[SCAN_GRID * SCAN_BLK];
__device__ int g_btot[SCAN_GRID];
__device__ int g_boff[SCAN_GRID];

// ---------------------------------------------------------------------------
// K0: zero the row histogram
// ---------------------------------------------------------------------------
__global__ void zero_cnt_kernel() {
    int i = blockIdx.x * blockDim.x + threadIdx.x;
    if (i < NN) g_cnt[i] = 0;
}

// ---------------------------------------------------------------------------
// K1: h0 = emb[x]; g_a = half(dropout(h0, u1)).  One thread per float4.
// ---------------------------------------------------------------------------
__global__ void embed_dropout_kernel(const int* __restrict__ x,
                                     const float* __restrict__ emb,
                                     const float* __restrict__ u1) {
    int t = blockIdx.x * blockDim.x + threadIdx.x;   // over N*32
    if (t >= NN * (DD / 4)) return;
    int i = t >> 5;
    int q = t & 31;
    int xi = x[i];
    float4 h = reinterpret_cast<const float4*>(emb + (size_t)xi * DD)[q];
    float4 u = reinterpret_cast<const float4*>(u1)[t];
    float gx = (u.x >= RATE) ? h.x * INV_KEEP : 0.f;
    float gy = (u.y >= RATE) ? h.y * INV_KEEP : 0.f;
    float gz = (u.z >= RATE) ? h.z * INV_KEEP : 0.f;
    float gw = (u.w >= RATE) ? h.w * INV_KEEP : 0.f;
    reinterpret_cast<float4*>(g_h0)[t] = h;
    __half2 p0 = __floats2half2_rn(gx, gy);
    __half2 p1 = __floats2half2_rn(gz, gw);
    uint2 packed = make_uint2(*reinterpret_cast<unsigned*>(&p0),
                              *reinterpret_cast<unsigned*>(&p1));
    reinterpret_cast<uint2*>(g_ga)[t] = packed;
}

// ---------------------------------------------------------------------------
// K2: row histogram
// ---------------------------------------------------------------------------
__global__ void hist_kernel(const int* __restrict__ rows) {
    int e = blockIdx.x * blockDim.x + threadIdx.x;
    if (e < EE) atomicAdd(&g_cnt[rows[e]], 1);
}

// ---------------------------------------------------------------------------
// K3a: per-block inclusive scan + block totals
// ---------------------------------------------------------------------------
__global__ void scan1_kernel() {
    __shared__ int s[SCAN_BLK];
    int tid = threadIdx.x;
    int i = blockIdx.x * SCAN_BLK + tid;
    int v = (i < NN) ? g_cnt[i] : 0;
    s[tid] = v;
    __syncthreads();
#pragma unroll
    for (int off = 1; off < SCAN_BLK; off <<= 1) {
        int add = (tid >= off) ? s[tid - off] : 0;
        __syncthreads();
        s[tid] += add;
        __syncthreads();
    }
    g_incl[i] = s[tid];
    if (tid == SCAN_BLK - 1) g_btot[blockIdx.x] = s[tid];
}

// ---------------------------------------------------------------------------
// K3b: parallel exclusive scan of the 98 block totals (one 128-thread block)
// ---------------------------------------------------------------------------
__global__ void scan2_kernel() {
    __shared__ int s[128];
    int tid = threadIdx.x;
    int v = (tid < SCAN_GRID) ? g_btot[tid] : 0;
    s[tid] = v;
    __syncthreads();
#pragma unroll
    for (int off = 1; off < 128; off <<= 1) {
        int add = (tid >= off) ? s[tid - off] : 0;
        __syncthreads();
        s[tid] += add;
        __syncthreads();
    }
    if (tid < SCAN_GRID) g_boff[tid] = s[tid] - v;   // exclusive
}

// ---------------------------------------------------------------------------
// K3c: row_ptr (exclusive) + cursor init
// ---------------------------------------------------------------------------
__global__ void scan3_kernel() {
    int i = blockIdx.x * SCAN_BLK + threadIdx.x;
    if (i < NN) {
        int ex = g_incl[i] - g_cnt[i] + g_boff[blockIdx.x];
        g_rowptr[i] = ex;
        g_cursor[i] = ex;
    }
    if (i == 0) g_rowptr[NN] = EE;
}

// ---------------------------------------------------------------------------
// K4: scatter edges into CSR order, packed {col, val}
// ---------------------------------------------------------------------------
__global__ void scatter_kernel(const int* __restrict__ rows,
                               const int* __restrict__ cols,
                               const float* __restrict__ vals) {
    int e = blockIdx.x * blockDim.x + threadIdx.x;
    if (e >= EE) return;
    int r = rows[e];
    int pos = atomicAdd(&g_cursor[r], 1);
    g_cv[pos] = make_uint2((unsigned)cols[e], __float_as_uint(vals[e]));
}

// ---------------------------------------------------------------------------
// K5/K6: CSR SpMM, warp per row, fp16 gathers, fp32 accumulation.
//   MODE 0: gather g_a; write h1 (fp32) AND g_b = half(dropout(h1,u2))
//   MODE 1: gather g_b; write out = (h0 + h1 + acc) / 3
// Each lane owns 4 channels -> one uint2 (4 halves) per gathered row.
// ---------------------------------------------------------------------------
__device__ __forceinline__ void fma_h4(float4& acc, float v, uint2 m) {
    __half2 p0 = *reinterpret_cast<__half2*>(&m.x);
    __half2 p1 = *reinterpret_cast<__half2*>(&m.y);
    float2 f0 = __half22float2(p0);
    float2 f1 = __half22float2(p1);
    acc.x += v * f0.x; acc.y += v * f0.y;
    acc.z += v * f1.x; acc.w += v * f1.y;
}

template <int MODE>
__global__ void spmm_csr_kernel(const float* __restrict__ u2,
                                float* __restrict__ out) {
    int gw   = (blockIdx.x * blockDim.x + threadIdx.x) >> 5;  // row
    int lane = threadIdx.x & 31;
    if (gw >= NN) return;

    int s = g_rowptr[gw];
    int e = g_rowptr[gw + 1];
    const uint2* gsrc =
        reinterpret_cast<const uint2*>(MODE == 0 ? g_ga : g_gb);

    float4 acc = make_float4(0.f, 0.f, 0.f, 0.f);

    for (int base = s; base < e; base += 32) {
        int j = base + lane;
        uint2 cv = make_uint2(0u, 0u);
        if (j < e) cv = g_cv[j];
        int cnt = min(32, e - base);

        int k = 0;
        for (; k + 4 <= cnt; k += 4) {
            int   c0 = __shfl_sync(0xffffffffu, (int)cv.x, k + 0);
            int   c1 = __shfl_sync(0xffffffffu, (int)cv.x, k + 1);
            int   c2 = __shfl_sync(0xffffffffu, (int)cv.x, k + 2);
            int   c3 = __shfl_sync(0xffffffffu, (int)cv.x, k + 3);
            float v0 = __uint_as_float(__shfl_sync(0xffffffffu, cv.y, k + 0));
            float v1 = __uint_as_float(__shfl_sync(0xffffffffu, cv.y, k + 1));
            float v2 = __uint_as_float(__shfl_sync(0xffffffffu, cv.y, k + 2));
            float v3 = __uint_as_float(__shfl_sync(0xffffffffu, cv.y, k + 3));
            uint2 m0 = gsrc[c0 * 32 + lane];
            uint2 m1 = gsrc[c1 * 32 + lane];
            uint2 m2 = gsrc[c2 * 32 + lane];
            uint2 m3 = gsrc[c3 * 32 + lane];
            fma_h4(acc, v0, m0);
            fma_h4(acc, v1, m1);
            fma_h4(acc, v2, m2);
            fma_h4(acc, v3, m3);
        }
        for (; k < cnt; k++) {
            int   c = __shfl_sync(0xffffffffu, (int)cv.x, k);
            float v = __uint_as_float(__shfl_sync(0xffffffffu, cv.y, k));
            uint2 m = gsrc[c * 32 + lane];
            fma_h4(acc, v, m);
        }
    }

    int t = gw * 32 + lane;
    if (MODE == 0) {
        reinterpret_cast<float4*>(g_h1)[t] = acc;
        float4 u = reinterpret_cast<const float4*>(u2)[t];
        float gx = (u.x >= RATE) ? acc.x * INV_KEEP : 0.f;
        float gy = (u.y >= RATE) ? acc.y * INV_KEEP : 0.f;
        float gz = (u.z >= RATE) ? acc.z * INV_KEEP : 0.f;
        float gw4 = (u.w >= RATE) ? acc.w * INV_KEEP : 0.f;
        __half2 p0 = __floats2half2_rn(gx, gy);
        __half2 p1 = __floats2half2_rn(gz, gw4);
        uint2 packed = make_uint2(*reinterpret_cast<unsigned*>(&p0),
                                  *reinterpret_cast<unsigned*>(&p1));
        reinterpret_cast<uint2*>(g_gb)[t] = packed;
    } else {
        float4 a = reinterpret_cast<const float4*>(g_h0)[t];
        float4 b = reinterpret_cast<const float4*>(g_h1)[t];
        const float kk = 1.0f / 3.0f;
        float4 o;
        o.x = (a.x + b.x + acc.x) * kk;
        o.y = (a.y + b.y + acc.y) * kk;
        o.z = (a.z + b.z + acc.z) * kk;
        o.w = (a.w + b.w + acc.w) * kk;
        reinterpret_cast<float4*>(out)[t] = o;
    }
}

// ---------------------------------------------------------------------------
// kernel_launch — graph-capturable pipeline
// inputs: 0:x(int32)[N] 1:rows[E] 2:cols[E] 3:A_vals[E] 4:emb[N*D] 5:u1 6:u2
// ---------------------------------------------------------------------------
extern "C" void kernel_launch(void* const* d_in, const int* in_sizes, int n_in,
                              void* d_out, int out_size) {
    const int*   x    = (const int*)  d_in[0];
    const int*   rows = (const int*)  d_in[1];
    const int*   cols = (const int*)  d_in[2];
    const float* vals = (const float*)d_in[3];
    const float* emb  = (const float*)d_in[4];
    const float* u1   = (const float*)d_in[5];
    const float* u2   = (const float*)d_in[6];
    float* out = (float*)d_out;

    const int TPB = 256;
    const int nd4_blocks  = (NN * (DD / 4) + TPB - 1) / TPB;  // 12500
    const int e_blocks    = (EE + TPB - 1) / TPB;             // 6250
    const int cnt_blocks  = (NN + TPB - 1) / TPB;             // 391
    const int spmm_blocks = (NN * 32 + TPB - 1) / TPB;        // 12500

    // CSR build
    zero_cnt_kernel<<<cnt_blocks, TPB>>>();
    hist_kernel<<<e_blocks, TPB>>>(rows);
    scan1_kernel<<<SCAN_GRID, SCAN_BLK>>>();
    scan2_kernel<<<1, 128>>>();
    scan3_kernel<<<SCAN_GRID, SCAN_BLK>>>();
    scatter_kernel<<<e_blocks, TPB>>>(rows, cols, vals);

    // Features
    embed_dropout_kernel<<<nd4_blocks, TPB>>>(x, emb, u1);

    // Layer 1: h1 = A g_a; g_b = half(dropout(h1,u2))   (fused epilogue)
    spmm_csr_kernel<0><<<spmm_blocks, TPB>>>(u2, out);
    // Layer 2: out = (h0 + h1 + A g_b) / 3               (fused epilogue)
    spmm_csr_kernel<1><<<spmm_blocks, TPB>>>(u2, out);
}

// round 8
// speedup vs baseline: 1.9753x; 1.2399x over previous
#include <cuda_runtime.h>
#include <cuda_fp16.h>
#include <cstdint>

// LightGCN_2: N=100000 nodes, D=128 channels, E=1600000 edges
#define NN 100000
#define DD 128
#define EE 1600000
#define RATE 0.1f
#define INV_KEEP (1.0f / 0.9f)

#define SCAN_BLK 1024
#define SCAN_GRID ((NN + SCAN_BLK - 1) / SCAN_BLK)   // 98

// ---------------------------------------------------------------------------
// Static device scratch (allocation-free rule: __device__ globals)
// ---------------------------------------------------------------------------
__device__ __align__(16) float  g_h0[NN * DD];      // h0 = emb[x]     (fp32)
__device__ __align__(16) float  g_h1[NN * DD];      // layer-1 output  (fp32)
__device__ __align__(16) __half g_ga[NN * DD];      // dropout(h0,u1)  (fp16)
__device__ __align__(16) __half g_gb[NN * DD];      // dropout(h1,u2)  (fp16)

__device__ __align__(8)  uint2 g_cv[EE];            // CSR payload {col, val bits}
__device__ int g_rank[EE];                          // arrival rank within row
__device__ int g_cnt[NN];                           // row histogram
__device__ int g_rowptr[NN + 1];                    // CSR row pointers
__device__ unsigned long long g_scanstate[SCAN_GRID]; // lookback: hi32=ready, lo32=total

// ---------------------------------------------------------------------------
// K1: h0 = emb[x]; g_a = half(dropout(h0,u1)); also resets cnt + scan state.
// ---------------------------------------------------------------------------
__global__ void embed_dropout_kernel(const int* __restrict__ x,
                                     const float* __restrict__ emb,
                                     const float* __restrict__ u1) {
    int t = blockIdx.x * blockDim.x + threadIdx.x;   // over N*32
    if (t < NN) g_cnt[t] = 0;
    if (t < SCAN_GRID) g_scanstate[t] = 0ull;
    if (t >= NN * (DD / 4)) return;
    int i = t >> 5;
    int q = t & 31;
    int xi = x[i];
    float4 h = reinterpret_cast<const float4*>(emb + (size_t)xi * DD)[q];
    float4 u = reinterpret_cast<const float4*>(u1)[t];
    float gx = (u.x >= RATE) ? h.x * INV_KEEP : 0.f;
    float gy = (u.y >= RATE) ? h.y * INV_KEEP : 0.f;
    float gz = (u.z >= RATE) ? h.z * INV_KEEP : 0.f;
    float gw = (u.w >= RATE) ? h.w * INV_KEEP : 0.f;
    reinterpret_cast<float4*>(g_h0)[t] = h;
    __half2 p0 = __floats2half2_rn(gx, gy);
    __half2 p1 = __floats2half2_rn(gz, gw);
    uint2 packed = make_uint2(*reinterpret_cast<unsigned*>(&p0),
                              *reinterpret_cast<unsigned*>(&p1));
    reinterpret_cast<uint2*>(g_ga)[t] = packed;
}

// ---------------------------------------------------------------------------
// K2: histogram + per-edge arrival rank (single atomic pass)
// ---------------------------------------------------------------------------
__global__ void hist_rank_kernel(const int* __restrict__ rows) {
    int e = blockIdx.x * blockDim.x + threadIdx.x;
    if (e >= EE) return;
    g_rank[e] = atomicAdd(&g_cnt[rows[e]], 1);
}

// ---------------------------------------------------------------------------
// K3: single-pass exclusive scan of g_cnt -> g_rowptr (decoupled lookback).
// 98 blocks, all co-resident on 148 SMs -> spin-wait is deadlock-free.
// ---------------------------------------------------------------------------
__global__ void scan_lookback_kernel() {
    __shared__ int s[SCAN_BLK];
    __shared__ int base_sh;
    int tid = threadIdx.x;
    int b = blockIdx.x;
    int i = b * SCAN_BLK + tid;
    int v = (i < NN) ? g_cnt[i] : 0;
    s[tid] = v;
    __syncthreads();
#pragma unroll
    for (int off = 1; off < SCAN_BLK; off <<= 1) {
        int add = (tid >= off) ? s[tid - off] : 0;
        __syncthreads();
        s[tid] += add;
        __syncthreads();
    }
    // publish this block's total (ready bit + value in one 64-bit word)
    if (tid == 0) {
        unsigned long long st = (1ull << 32) | (unsigned)s[SCAN_BLK - 1];
        atomicExch(&g_scanstate[b], st);
    }
    // lookback: warp-parallel poll of all predecessor totals
    if (tid < 32) {
        int base = 0;
        for (int p = tid; p < b; p += 32) {
            unsigned long long st;
            do {
                st = *(volatile unsigned long long*)&g_scanstate[p];
            } while (!(st >> 32));
            base += (int)(st & 0xffffffffu);
        }
#pragma unroll
        for (int o = 16; o; o >>= 1)
            base += __shfl_down_sync(0xffffffffu, base, o);
        if (tid == 0) base_sh = base;
    }
    __syncthreads();
    if (i < NN) g_rowptr[i] = base_sh + s[tid] - v;   // exclusive
    if (i == 0) g_rowptr[NN] = EE;
}

// ---------------------------------------------------------------------------
// K4: scatter edges into CSR order (no atomics: rowptr + precomputed rank)
// ---------------------------------------------------------------------------
__global__ void scatter_kernel(const int* __restrict__ rows,
                               const int* __restrict__ cols,
                               const float* __restrict__ vals) {
    int e = blockIdx.x * blockDim.x + threadIdx.x;
    if (e >= EE) return;
    int pos = g_rowptr[rows[e]] + g_rank[e];
    g_cv[pos] = make_uint2((unsigned)cols[e], __float_as_uint(vals[e]));
}

// ---------------------------------------------------------------------------
// K5/K6: CSR SpMM, warp per row. Edge metadata via warp-uniform broadcast
// loads (no shfl), 8 gathers in flight, fp16 gathers, fp32 accumulation.
//   MODE 0: gather g_a; write h1 (fp32) AND g_b = half(dropout(h1,u2))
//   MODE 1: gather g_b; write out = (h0 + h1 + acc) / 3
// ---------------------------------------------------------------------------
__device__ __forceinline__ void fma_h4(float4& acc, float v, uint2 m) {
    __half2 p0 = *reinterpret_cast<__half2*>(&m.x);
    __half2 p1 = *reinterpret_cast<__half2*>(&m.y);
    float2 f0 = __half22float2(p0);
    float2 f1 = __half22float2(p1);
    acc.x += v * f0.x; acc.y += v * f0.y;
    acc.z += v * f1.x; acc.w += v * f1.y;
}

template <int MODE>
__global__ void spmm_csr_kernel(const float* __restrict__ u2,
                                float* __restrict__ out) {
    int gw   = (blockIdx.x * blockDim.x + threadIdx.x) >> 5;  // row
    int lane = threadIdx.x & 31;
    if (gw >= NN) return;

    int s = g_rowptr[gw];
    int e = g_rowptr[gw + 1];
    const uint2* __restrict__ cvp = g_cv;
    const uint2* __restrict__ gsrc =
        reinterpret_cast<const uint2*>(MODE == 0 ? g_ga : g_gb);

    float4 acc = make_float4(0.f, 0.f, 0.f, 0.f);

    int j = s;
    for (; j + 8 <= e; j += 8) {
        uint2 cv[8];
#pragma unroll
        for (int k = 0; k < 8; k++) cv[k] = cvp[j + k];      // uniform bcast
        uint2 m[8];
#pragma unroll
        for (int k = 0; k < 8; k++) m[k] = gsrc[(int)cv[k].x * 32 + lane];
#pragma unroll
        for (int k = 0; k < 8; k++)
            fma_h4(acc, __uint_as_float(cv[k].y), m[k]);
    }
    if (j + 4 <= e) {
        uint2 cv[4];
#pragma unroll
        for (int k = 0; k < 4; k++) cv[k] = cvp[j + k];
        uint2 m[4];
#pragma unroll
        for (int k = 0; k < 4; k++) m[k] = gsrc[(int)cv[k].x * 32 + lane];
#pragma unroll
        for (int k = 0; k < 4; k++)
            fma_h4(acc, __uint_as_float(cv[k].y), m[k]);
        j += 4;
    }
    for (; j < e; j++) {
        uint2 c = cvp[j];
        uint2 m = gsrc[(int)c.x * 32 + lane];
        fma_h4(acc, __uint_as_float(c.y), m);
    }

    int t = gw * 32 + lane;
    if (MODE == 0) {
        reinterpret_cast<float4*>(g_h1)[t] = acc;
        float4 u = reinterpret_cast<const float4*>(u2)[t];
        float gx  = (u.x >= RATE) ? acc.x * INV_KEEP : 0.f;
        float gy  = (u.y >= RATE) ? acc.y * INV_KEEP : 0.f;
        float gz  = (u.z >= RATE) ? acc.z * INV_KEEP : 0.f;
        float gw4 = (u.w >= RATE) ? acc.w * INV_KEEP : 0.f;
        __half2 p0 = __floats2half2_rn(gx, gy);
        __half2 p1 = __floats2half2_rn(gz, gw4);
        uint2 packed = make_uint2(*reinterpret_cast<unsigned*>(&p0),
                                  *reinterpret_cast<unsigned*>(&p1));
        reinterpret_cast<uint2*>(g_gb)[t] = packed;
    } else {
        float4 a = reinterpret_cast<const float4*>(g_h0)[t];
        float4 b = reinterpret_cast<const float4*>(g_h1)[t];
        const float kk = 1.0f / 3.0f;
        float4 o;
        o.x = (a.x + b.x + acc.x) * kk;
        o.y = (a.y + b.y + acc.y) * kk;
        o.z = (a.z + b.z + acc.z) * kk;
        o.w = (a.w + b.w + acc.w) * kk;
        reinterpret_cast<float4*>(out)[t] = o;
    }
}

// ---------------------------------------------------------------------------
// kernel_launch — graph-capturable pipeline (6 launches)
// inputs: 0:x(int32)[N] 1:rows[E] 2:cols[E] 3:A_vals[E] 4:emb[N*D] 5:u1 6:u2
// ---------------------------------------------------------------------------
extern "C" void kernel_launch(void* const* d_in, const int* in_sizes, int n_in,
                              void* d_out, int out_size) {
    const int*   x    = (const int*)  d_in[0];
    const int*   rows = (const int*)  d_in[1];
    const int*   cols = (const int*)  d_in[2];
    const float* vals = (const float*)d_in[3];
    const float* emb  = (const float*)d_in[4];
    const float* u1   = (const float*)d_in[5];
    const float* u2   = (const float*)d_in[6];
    float* out = (float*)d_out;

    const int TPB = 256;
    const int nd4_blocks  = (NN * (DD / 4) + TPB - 1) / TPB;  // 12500
    const int e_blocks    = (EE + TPB - 1) / TPB;             // 6250
    const int spmm_blocks = (NN * 32 + TPB - 1) / TPB;        // 12500

    embed_dropout_kernel<<<nd4_blocks, TPB>>>(x, emb, u1);    // + cnt/state reset
    hist_rank_kernel<<<e_blocks, TPB>>>(rows);
    scan_lookback_kernel<<<SCAN_GRID, SCAN_BLK>>>();
    scatter_kernel<<<e_blocks, TPB>>>(rows, cols, vals);

    spmm_csr_kernel<0><<<spmm_blocks, TPB>>>(u2, out);
    spmm_csr_kernel<1><<<spmm_blocks, TPB>>>(u2, out);
}